// round 2
// baseline (speedup 1.0000x reference)
#include <cuda_runtime.h>

// ---------------------------------------------------------------------------
// GAT layer: out = relu( segsum_dst( softmax_dst(Q[dst]·K[src]/sqrt(32)) * V[src] ) @ Wo^T + bo )
// Pipeline: detect idx dtype -> zero -> QKV GEMM -> edge scores + global max
//           -> exp + per-dst sum -> message scatter (red.v4) -> output GEMM(+relu)
// ---------------------------------------------------------------------------

#define MAXN 50048
#define MAXE 1600000

__device__ float    g_Q[MAXN * 128];
__device__ float    g_K[MAXN * 128];
__device__ float    g_V[MAXN * 128];
__device__ float    g_agg[MAXN * 128];
__device__ float    g_scores[MAXE * 4];
__device__ float    g_sum[MAXN * 4];
__device__ unsigned g_maxbits;
__device__ int      g_idx64;     // 1 if edge_index is int64, 0 if int32

// order-preserving float<->uint mapping for atomicMax on signed floats
__device__ __forceinline__ unsigned fenc(float f) {
    unsigned u = __float_as_uint(f);
    return (u & 0x80000000u) ? ~u : (u | 0x80000000u);
}
__device__ __forceinline__ float fdec(unsigned u) {
    return (u & 0x80000000u) ? __uint_as_float(u & 0x7FFFFFFFu)
                             : __uint_as_float(~u);
}

// Load edge index element at logical position pos (0..2E-1), dtype-robust.
__device__ __forceinline__ int load_idx(const void* ei, long long pos, int M) {
    int v;
    if (g_idx64) v = (int)((const long long*)ei)[pos];
    else         v = ((const int*)ei)[pos];
    // defensive clamp: never fault even if detection is wrong
    v = v < 0 ? 0 : (v >= M ? M - 1 : v);
    return v;
}

// ---------------------------------------------------------------------------
// Detect whether edge_index is int64 (upper words all zero) or int32.
// ---------------------------------------------------------------------------
__global__ void detect_kernel(const unsigned* __restrict__ ei_u32) {
    if (threadIdx.x == 0 && blockIdx.x == 0) {
        int is64 = 1;
        for (int i = 0; i < 128; i++)
            if (ei_u32[2 * i + 1] != 0u) { is64 = 0; break; }
        g_idx64 = is64;
    }
}

// ---------------------------------------------------------------------------
__global__ void zero_scratch(int M) {
    long long tid = (long long)blockIdx.x * blockDim.x + threadIdx.x;
    long long gs  = (long long)gridDim.x * blockDim.x;
    int n_agg = M * 128;
    for (long long i = tid; i < n_agg; i += gs) g_agg[i] = 0.f;
    int n_sum = M * 4;
    for (long long i = tid; i < n_sum; i += gs) g_sum[i] = 0.f;
    if (tid == 0) g_maxbits = 0u;
}

// ---------------------------------------------------------------------------
// Tiled fp32 GEMM: C[M,128] = A[M,128] @ B[128,128]^T + bias (B row-major, rows = out ch)
// BM=BN=128, BK=32, 256 threads, 8x8 register tile per thread.
// blockIdx.y selects among up to 3 (B, bias, C) triples (fused Q/K/V projection).
// ---------------------------------------------------------------------------
#define BM 128
#define BN 128
#define BK 32

__global__ __launch_bounds__(256, 2)
void gemm_kernel(const float* __restrict__ A, int M,
                 const float* __restrict__ Ba, const float* __restrict__ Bb,
                 const float* __restrict__ Bc,
                 const float* __restrict__ ba, const float* __restrict__ bb,
                 const float* __restrict__ bc,
                 float* __restrict__ Ca, float* __restrict__ Cb,
                 float* __restrict__ Cc,
                 int relu)
{
    __shared__ float As[BK][BM + 4];
    __shared__ float Bs[BK][BN + 4];

    const float* B;
    const float* bias;
    float*       C;
    if (blockIdx.y == 0)      { B = Ba; bias = ba; C = Ca; }
    else if (blockIdx.y == 1) { B = Bb; bias = bb; C = Cb; }
    else                      { B = Bc; bias = bc; C = Cc; }

    int tid = threadIdx.x;
    int tx  = tid & 15;      // 0..15 -> output cols (8 each)
    int ty  = tid >> 4;      // 0..15 -> output rows (8 each)
    int m0  = blockIdx.x * BM;

    float acc[8][8];
#pragma unroll
    for (int r = 0; r < 8; r++)
#pragma unroll
        for (int c = 0; c < 8; c++) acc[r][c] = 0.f;

    for (int k0 = 0; k0 < 128; k0 += BK) {
#pragma unroll
        for (int i = 0; i < 4; i++) {
            int idx = tid + i * 256;     // 0..1023
            int row = idx & 127;
            int kq  = idx >> 7;          // 0..7
            float4 v = make_float4(0.f, 0.f, 0.f, 0.f);
            int m = m0 + row;
            if (m < M)
                v = *(const float4*)(A + (size_t)m * 128 + k0 + kq * 4);
            As[kq * 4 + 0][row] = v.x;
            As[kq * 4 + 1][row] = v.y;
            As[kq * 4 + 2][row] = v.z;
            As[kq * 4 + 3][row] = v.w;
            float4 w = *(const float4*)(B + (size_t)row * 128 + k0 + kq * 4);
            Bs[kq * 4 + 0][row] = w.x;
            Bs[kq * 4 + 1][row] = w.y;
            Bs[kq * 4 + 2][row] = w.z;
            Bs[kq * 4 + 3][row] = w.w;
        }
        __syncthreads();

#pragma unroll
        for (int kk = 0; kk < BK; kk++) {
            float4 a0 = *(const float4*)&As[kk][ty * 8];
            float4 a1 = *(const float4*)&As[kk][ty * 8 + 4];
            float4 b0 = *(const float4*)&Bs[kk][tx * 8];
            float4 b1 = *(const float4*)&Bs[kk][tx * 8 + 4];
            float a[8] = {a0.x, a0.y, a0.z, a0.w, a1.x, a1.y, a1.z, a1.w};
            float b[8] = {b0.x, b0.y, b0.z, b0.w, b1.x, b1.y, b1.z, b1.w};
#pragma unroll
            for (int r = 0; r < 8; r++)
#pragma unroll
                for (int c = 0; c < 8; c++)
                    acc[r][c] = fmaf(a[r], b[c], acc[r][c]);
        }
        __syncthreads();
    }

#pragma unroll
    for (int r = 0; r < 8; r++) {
        int m = m0 + ty * 8 + r;
        if (m >= M) continue;
#pragma unroll
        for (int c = 0; c < 8; c += 4) {
            int n = tx * 8 + c;
            float4 o;
            o.x = acc[r][c + 0] + bias[n + 0];
            o.y = acc[r][c + 1] + bias[n + 1];
            o.z = acc[r][c + 2] + bias[n + 2];
            o.w = acc[r][c + 3] + bias[n + 3];
            if (relu) {
                o.x = fmaxf(o.x, 0.f);
                o.y = fmaxf(o.y, 0.f);
                o.z = fmaxf(o.z, 0.f);
                o.w = fmaxf(o.w, 0.f);
            }
            *(float4*)(C + (size_t)m * 128 + n) = o;
        }
    }
}

// ---------------------------------------------------------------------------
// Per (edge, head): score = Q[dst,h]·K[src,h] / sqrt(32); track global max.
// ---------------------------------------------------------------------------
__global__ void edge_scores_kernel(const void* __restrict__ ei, int E, int M)
{
    int t = blockIdx.x * blockDim.x + threadIdx.x;
    float s = -3.4e38f;
    if (t < 4 * E) {
        int e = t >> 2, h = t & 3;
        int src = load_idx(ei, e, M);
        int dst = load_idx(ei, (long long)E + e, M);
        const float4* q = (const float4*)(g_Q + (size_t)dst * 128 + h * 32);
        const float4* k = (const float4*)(g_K + (size_t)src * 128 + h * 32);
        float acc = 0.f;
#pragma unroll
        for (int i = 0; i < 8; i++) {
            float4 a = q[i], b = k[i];
            acc = fmaf(a.x, b.x, acc);
            acc = fmaf(a.y, b.y, acc);
            acc = fmaf(a.z, b.z, acc);
            acc = fmaf(a.w, b.w, acc);
        }
        s = acc * 0.17677669529663687f;   // 1/sqrt(32)
        g_scores[t] = s;
    }
    // block max reduce -> single atomic per block
    float m = s;
#pragma unroll
    for (int o = 16; o; o >>= 1) m = fmaxf(m, __shfl_xor_sync(0xFFFFFFFFu, m, o));
    __shared__ float wmax[8];
    if ((threadIdx.x & 31) == 0) wmax[threadIdx.x >> 5] = m;
    __syncthreads();
    if (threadIdx.x < 8) {
        m = wmax[threadIdx.x];
#pragma unroll
        for (int o = 4; o; o >>= 1) m = fmaxf(m, __shfl_xor_sync(0xFFu, m, o));
        if (threadIdx.x == 0) atomicMax(&g_maxbits, fenc(m));
    }
}

// ---------------------------------------------------------------------------
// Per (edge, head): p = exp(score - gmax); store p; per-dst sum via RED.
// ---------------------------------------------------------------------------
__global__ void exp_sum_kernel(const void* __restrict__ ei, int E, int M)
{
    int t = blockIdx.x * blockDim.x + threadIdx.x;
    if (t >= 4 * E) return;
    int e = t >> 2, h = t & 3;
    int dst = load_idx(ei, (long long)E + e, M);
    float m = fdec(g_maxbits);
    float p = expf(g_scores[t] - m);
    g_scores[t] = p;
    atomicAdd(&g_sum[dst * 4 + h], p);
}

// ---------------------------------------------------------------------------
// Warp per edge: attn = p/(sum[dst]+1e-8); agg[dst] += attn*V[src] via red.v4
// ---------------------------------------------------------------------------
__global__ void message_kernel(const void* __restrict__ ei, int E, int M)
{
    long long gt = (long long)blockIdx.x * blockDim.x + threadIdx.x;
    long long e = gt >> 5;
    int lane = (int)(gt & 31);
    if (e >= E) return;
    int src = load_idx(ei, e, M);
    int dst = load_idx(ei, (long long)E + e, M);
    int h = lane >> 3;
    float p    = g_scores[e * 4 + h];
    float ssum = g_sum[(size_t)dst * 4 + h];
    float attn = p / (ssum + 1e-8f);
    float4 v = ((const float4*)(g_V + (size_t)src * 128))[lane];
    float* dp = g_agg + (size_t)dst * 128 + lane * 4;
    float mx = v.x * attn, my = v.y * attn, mz = v.z * attn, mw = v.w * attn;
    asm volatile("red.global.add.v4.f32 [%0], {%1,%2,%3,%4};"
                 :: "l"(dp), "f"(mx), "f"(my), "f"(mz), "f"(mw)
                 : "memory");
}

// ---------------------------------------------------------------------------
extern "C" void kernel_launch(void* const* d_in, const int* in_sizes, int n_in,
                              void* d_out, int out_size)
{
    const float* x  = (const float*)d_in[0];
    const void*  ei = d_in[1];
    const float* Wq = (const float*)d_in[2];
    const float* bq = (const float*)d_in[3];
    const float* Wk = (const float*)d_in[4];
    const float* bk = (const float*)d_in[5];
    const float* Wv = (const float*)d_in[6];
    const float* bv = (const float*)d_in[7];
    const float* Wo = (const float*)d_in[8];
    const float* bo = (const float*)d_in[9];
    float*       out = (float*)d_out;

    int M = in_sizes[0] / 128;   // nodes
    int E = in_sizes[1] / 2;     // edges

    float *pQ, *pK, *pV, *pAgg;
    cudaGetSymbolAddress((void**)&pQ,   g_Q);
    cudaGetSymbolAddress((void**)&pK,   g_K);
    cudaGetSymbolAddress((void**)&pV,   g_V);
    cudaGetSymbolAddress((void**)&pAgg, g_agg);

    detect_kernel<<<1, 32>>>((const unsigned*)ei);
    zero_scratch<<<512, 256>>>(M);

    dim3 gqkv((M + BM - 1) / BM, 3);
    gemm_kernel<<<gqkv, 256>>>(x, M, Wq, Wk, Wv, bq, bk, bv, pQ, pK, pV, 0);

    int th = E * 4;
    edge_scores_kernel<<<(th + 255) / 256, 256>>>(ei, E, M);
    exp_sum_kernel<<<(th + 255) / 256, 256>>>(ei, E, M);

    long long mt = (long long)E * 32;
    message_kernel<<<(int)((mt + 255) / 256), 256>>>(ei, E, M);

    dim3 gout((M + BM - 1) / BM, 1);
    gemm_kernel<<<gout, 256>>>(pAgg, M, Wo, Wo, Wo, bo, bo, bo, out, out, out, 1);
}

// round 3
// speedup vs baseline: 1.5412x; 1.5412x over previous
#include <cuda_runtime.h>

// ---------------------------------------------------------------------------
// GAT layer, fused:
//   out = relu( (segsum_dst(exp(s)*V[src]) / (segsum_dst(exp(s))+1e-8)) @ Wo^T + bo )
// Pipeline: detect idx dtype -> zero -> QKV GEMM
//           -> ONE fused edge pass (score, exp, sum-RED, unnormalized V scatter)
//           -> output GEMM with per-(node,head) normalization fused into A load
// Global-max shift dropped: cancels in the ratio except through +1e-8 (~2e-9 rel).
// ---------------------------------------------------------------------------

#define MAXN 50048
#define MAXE 1600000

__device__ float g_Q[MAXN * 128];
__device__ float g_K[MAXN * 128];
__device__ float g_V[MAXN * 128];
__device__ float g_agg[MAXN * 128];
__device__ float g_sum[MAXN * 4];
__device__ int   g_idx64;     // 1 if edge_index is int64, 0 if int32

// Load edge index element at logical position pos (0..2E-1), dtype-robust.
__device__ __forceinline__ int load_idx(const void* ei, long long pos, int M) {
    int v;
    if (g_idx64) v = (int)((const long long*)ei)[pos];
    else         v = ((const int*)ei)[pos];
    v = v < 0 ? 0 : (v >= M ? M - 1 : v);   // defensive clamp
    return v;
}

// ---------------------------------------------------------------------------
// Detect whether edge_index is int64 (upper words all zero) or int32.
// ---------------------------------------------------------------------------
__global__ void detect_kernel(const unsigned* __restrict__ ei_u32) {
    if (threadIdx.x == 0 && blockIdx.x == 0) {
        int is64 = 1;
        for (int i = 0; i < 128; i++)
            if (ei_u32[2 * i + 1] != 0u) { is64 = 0; break; }
        g_idx64 = is64;
    }
}

// ---------------------------------------------------------------------------
__global__ void zero_scratch(int M) {
    long long tid = (long long)blockIdx.x * blockDim.x + threadIdx.x;
    long long gs  = (long long)gridDim.x * blockDim.x;
    int n_agg = M * 128;
    for (long long i = tid; i < n_agg; i += gs) g_agg[i] = 0.f;
    int n_sum = M * 4;
    for (long long i = tid; i < n_sum; i += gs) g_sum[i] = 0.f;
}

// ---------------------------------------------------------------------------
// Tiled fp32 GEMM: C[M,128] = A[M,128] @ B[128,128]^T + bias.
// If normsum != null: A row m, cols [32h,32h+32) are divided by (normsum[m*4+h]+1e-8)
// at load time (deferred softmax normalization). relu flag for the output proj.
// blockIdx.y selects among up to 3 (B, bias, C) triples (fused QKV).
// ---------------------------------------------------------------------------
#define BM 128
#define BN 128
#define BK 32

__global__ __launch_bounds__(256, 2)
void gemm_kernel(const float* __restrict__ A, int M,
                 const float* __restrict__ Ba, const float* __restrict__ Bb,
                 const float* __restrict__ Bc,
                 const float* __restrict__ ba, const float* __restrict__ bb,
                 const float* __restrict__ bc,
                 float* __restrict__ Ca, float* __restrict__ Cb,
                 float* __restrict__ Cc,
                 const float* __restrict__ normsum,
                 int relu)
{
    __shared__ float As[BK][BM + 4];
    __shared__ float Bs[BK][BN + 4];

    const float* B;
    const float* bias;
    float*       C;
    if (blockIdx.y == 0)      { B = Ba; bias = ba; C = Ca; }
    else if (blockIdx.y == 1) { B = Bb; bias = bb; C = Cb; }
    else                      { B = Bc; bias = bc; C = Cc; }

    int tid = threadIdx.x;
    int tx  = tid & 15;
    int ty  = tid >> 4;
    int m0  = blockIdx.x * BM;

    float acc[8][8];
#pragma unroll
    for (int r = 0; r < 8; r++)
#pragma unroll
        for (int c = 0; c < 8; c++) acc[r][c] = 0.f;

    for (int k0 = 0; k0 < 128; k0 += BK) {
#pragma unroll
        for (int i = 0; i < 4; i++) {
            int idx = tid + i * 256;     // 0..1023
            int row = idx & 127;
            int kq  = idx >> 7;          // 0..7
            float4 v = make_float4(0.f, 0.f, 0.f, 0.f);
            int m = m0 + row;
            if (m < M) {
                v = *(const float4*)(A + (size_t)m * 128 + k0 + kq * 4);
                if (normsum) {
                    int h = (k0 + kq * 4) >> 5;   // head for these 4 k's
                    float inv = 1.f / (normsum[m * 4 + h] + 1e-8f);
                    v.x *= inv; v.y *= inv; v.z *= inv; v.w *= inv;
                }
            }
            As[kq * 4 + 0][row] = v.x;
            As[kq * 4 + 1][row] = v.y;
            As[kq * 4 + 2][row] = v.z;
            As[kq * 4 + 3][row] = v.w;
            float4 w = *(const float4*)(B + (size_t)row * 128 + k0 + kq * 4);
            Bs[kq * 4 + 0][row] = w.x;
            Bs[kq * 4 + 1][row] = w.y;
            Bs[kq * 4 + 2][row] = w.z;
            Bs[kq * 4 + 3][row] = w.w;
        }
        __syncthreads();

#pragma unroll
        for (int kk = 0; kk < BK; kk++) {
            float4 a0 = *(const float4*)&As[kk][ty * 8];
            float4 a1 = *(const float4*)&As[kk][ty * 8 + 4];
            float4 b0 = *(const float4*)&Bs[kk][tx * 8];
            float4 b1 = *(const float4*)&Bs[kk][tx * 8 + 4];
            float a[8] = {a0.x, a0.y, a0.z, a0.w, a1.x, a1.y, a1.z, a1.w};
            float b[8] = {b0.x, b0.y, b0.z, b0.w, b1.x, b1.y, b1.z, b1.w};
#pragma unroll
            for (int r = 0; r < 8; r++)
#pragma unroll
                for (int c = 0; c < 8; c++)
                    acc[r][c] = fmaf(a[r], b[c], acc[r][c]);
        }
        __syncthreads();
    }

#pragma unroll
    for (int r = 0; r < 8; r++) {
        int m = m0 + ty * 8 + r;
        if (m >= M) continue;
#pragma unroll
        for (int c = 0; c < 8; c += 4) {
            int n = tx * 8 + c;
            float4 o;
            o.x = acc[r][c + 0] + bias[n + 0];
            o.y = acc[r][c + 1] + bias[n + 1];
            o.z = acc[r][c + 2] + bias[n + 2];
            o.w = acc[r][c + 3] + bias[n + 3];
            if (relu) {
                o.x = fmaxf(o.x, 0.f);
                o.y = fmaxf(o.y, 0.f);
                o.z = fmaxf(o.z, 0.f);
                o.w = fmaxf(o.w, 0.f);
            }
            *(float4*)(C + (size_t)m * 128 + n) = o;
        }
    }
}

// ---------------------------------------------------------------------------
// Fused edge pass, one warp per edge:
//   lane l loads float4 l of Q[dst], K[src]  (coalesced 512B rows)
//   per-head dot via 3x shfl_xor within 8-lane groups
//   p = exp(score)  (global-max shift dropped; cancels in the ratio)
//   group-leader lanes RED p into g_sum[dst*4+h]
//   all lanes RED.v4 p * V[src] into g_agg[dst]  (unnormalized)
// ---------------------------------------------------------------------------
__global__ void edge_fused_kernel(const void* __restrict__ ei, int E, int M)
{
    long long gt = (long long)blockIdx.x * blockDim.x + threadIdx.x;
    long long e = gt >> 5;
    int lane = (int)(gt & 31);
    if (e >= E) return;

    int src = load_idx(ei, e, M);
    int dst = load_idx(ei, (long long)E + e, M);

    float4 q = ((const float4*)(g_Q + (size_t)dst * 128))[lane];
    float4 k = ((const float4*)(g_K + (size_t)src * 128))[lane];
    float part = q.x * k.x + q.y * k.y + q.z * k.z + q.w * k.w;
    part += __shfl_xor_sync(0xFFFFFFFFu, part, 1);
    part += __shfl_xor_sync(0xFFFFFFFFu, part, 2);
    part += __shfl_xor_sync(0xFFFFFFFFu, part, 4);
    // all lanes in each 8-lane group now hold their head's full dot
    float p = expf(part * 0.17677669529663687f);   // 1/sqrt(32)

    if ((lane & 7) == 0) {
        float* sp = g_sum + (size_t)dst * 4 + (lane >> 3);
        asm volatile("red.global.add.f32 [%0], %1;" :: "l"(sp), "f"(p) : "memory");
    }

    float4 v = ((const float4*)(g_V + (size_t)src * 128))[lane];
    float* dp = g_agg + (size_t)dst * 128 + lane * 4;
    asm volatile("red.global.add.v4.f32 [%0], {%1,%2,%3,%4};"
                 :: "l"(dp), "f"(v.x * p), "f"(v.y * p), "f"(v.z * p), "f"(v.w * p)
                 : "memory");
}

// ---------------------------------------------------------------------------
extern "C" void kernel_launch(void* const* d_in, const int* in_sizes, int n_in,
                              void* d_out, int out_size)
{
    const float* x  = (const float*)d_in[0];
    const void*  ei = d_in[1];
    const float* Wq = (const float*)d_in[2];
    const float* bq = (const float*)d_in[3];
    const float* Wk = (const float*)d_in[4];
    const float* bk = (const float*)d_in[5];
    const float* Wv = (const float*)d_in[6];
    const float* bv = (const float*)d_in[7];
    const float* Wo = (const float*)d_in[8];
    const float* bo = (const float*)d_in[9];
    float*       out = (float*)d_out;

    int M = in_sizes[0] / 128;   // nodes
    int E = in_sizes[1] / 2;     // edges

    float *pQ, *pK, *pV, *pAgg, *pSum;
    cudaGetSymbolAddress((void**)&pQ,   g_Q);
    cudaGetSymbolAddress((void**)&pK,   g_K);
    cudaGetSymbolAddress((void**)&pV,   g_V);
    cudaGetSymbolAddress((void**)&pAgg, g_agg);
    cudaGetSymbolAddress((void**)&pSum, g_sum);

    detect_kernel<<<1, 32>>>((const unsigned*)ei);
    zero_scratch<<<512, 256>>>(M);

    dim3 gqkv((M + BM - 1) / BM, 3);
    gemm_kernel<<<gqkv, 256>>>(x, M, Wq, Wk, Wv, bq, bk, bv,
                               pQ, pK, pV, (const float*)0, 0);

    long long wt = (long long)E * 32;
    edge_fused_kernel<<<(int)((wt + 255) / 256), 256>>>(ei, E, M);

    dim3 gout((M + BM - 1) / BM, 1);
    gemm_kernel<<<gout, 256>>>(pAgg, M, Wo, Wo, Wo, bo, bo, bo,
                               out, out, out, pSum, 1);
}

// round 4
// speedup vs baseline: 1.9838x; 1.2871x over previous
#include <cuda_runtime.h>

// ---------------------------------------------------------------------------
// GAT layer, CSR-gather version:
//   1. detect idx dtype, zero degree counters
//   2. QKV GEMM (fused 3-in-1)
//   3. counting sort edges by dst: histogram -> scan -> scatter (src ids)
//   4. aggregate: warp per dst; gather K/V[src], softmax accumulate in regs,
//      write normalized agg row (no atomics, no global max — cancels in ratio)
//   5. output GEMM + bias + relu
// ---------------------------------------------------------------------------

#define MAXN 50048
#define MAXE 1600000

__device__ float g_Q[MAXN * 128];
__device__ float g_K[MAXN * 128];
__device__ float g_V[MAXN * 128];
__device__ float g_agg[MAXN * 128];
__device__ int   g_off[MAXN + 1];   // CSR row starts
__device__ int   g_cur[MAXN];       // scatter cursors; == row end after sort
__device__ int   g_srcs[MAXE];      // src ids sorted by dst
__device__ int   g_idx64;           // 1 if edge_index is int64, 0 if int32

__device__ __forceinline__ int load_idx(const void* ei, long long pos, int M) {
    int v;
    if (g_idx64) v = (int)((const long long*)ei)[pos];
    else         v = ((const int*)ei)[pos];
    v = v < 0 ? 0 : (v >= M ? M - 1 : v);   // defensive clamp
    return v;
}

// ---------------------------------------------------------------------------
__global__ void detect_kernel(const unsigned* __restrict__ ei_u32) {
    if (threadIdx.x == 0 && blockIdx.x == 0) {
        int is64 = 1;
        for (int i = 0; i < 128; i++)
            if (ei_u32[2 * i + 1] != 0u) { is64 = 0; break; }
        g_idx64 = is64;
    }
}

__global__ void zero_deg(int M) {
    int t = blockIdx.x * blockDim.x + threadIdx.x;
    if (t < M) g_off[t] = 0;          // reuse g_off as degree counter
    if (t == 0) g_off[M] = 0;
}

// histogram of dst
__global__ void hist_kernel(const void* __restrict__ ei, int E, int M) {
    int t = blockIdx.x * blockDim.x + threadIdx.x;
    if (t >= E) return;
    int dst = load_idx(ei, (long long)E + t, M);
    atomicAdd(&g_off[dst], 1);
}

// single-block exclusive scan over g_off[0..M) (degrees) -> offsets; g_cur = copy
__global__ void scan_kernel(int M) {
    __shared__ int smem[1024];
    __shared__ int carry_s;
    int tid = threadIdx.x;
    if (tid == 0) carry_s = 0;
    __syncthreads();
    for (int base = 0; base < M; base += 1024) {
        int v = (base + tid < M) ? g_off[base + tid] : 0;
        smem[tid] = v;
        __syncthreads();
#pragma unroll
        for (int o = 1; o < 1024; o <<= 1) {
            int t2 = (tid >= o) ? smem[tid - o] : 0;
            __syncthreads();
            smem[tid] += t2;
            __syncthreads();
        }
        int incl  = smem[tid];
        int carry = carry_s;
        if (base + tid < M) {
            int excl = carry + incl - v;
            g_off[base + tid] = excl;
            g_cur[base + tid] = excl;
        }
        __syncthreads();
        if (tid == 1023) carry_s = carry + incl;
        __syncthreads();
    }
    if (tid == 0) g_off[M] = carry_s;
}

// scatter src ids into dst-sorted order
__global__ void scatter_kernel(const void* __restrict__ ei, int E, int M) {
    int t = blockIdx.x * blockDim.x + threadIdx.x;
    if (t >= E) return;
    int src = load_idx(ei, t, M);
    int dst = load_idx(ei, (long long)E + t, M);
    int pos = atomicAdd(&g_cur[dst], 1);
    g_srcs[pos] = src;
}

// ---------------------------------------------------------------------------
// Tiled fp32 GEMM: C[M,128] = A[M,128] @ B[128,128]^T + bias (+relu).
// blockIdx.y selects among up to 3 (B, bias, C) triples (fused QKV).
// ---------------------------------------------------------------------------
#define BM 128
#define BN 128
#define BK 32

__global__ __launch_bounds__(256, 2)
void gemm_kernel(const float* __restrict__ A, int M,
                 const float* __restrict__ Ba, const float* __restrict__ Bb,
                 const float* __restrict__ Bc,
                 const float* __restrict__ ba, const float* __restrict__ bb,
                 const float* __restrict__ bc,
                 float* __restrict__ Ca, float* __restrict__ Cb,
                 float* __restrict__ Cc,
                 int relu)
{
    __shared__ float As[BK][BM + 4];
    __shared__ float Bs[BK][BN + 4];

    const float* B;
    const float* bias;
    float*       C;
    if (blockIdx.y == 0)      { B = Ba; bias = ba; C = Ca; }
    else if (blockIdx.y == 1) { B = Bb; bias = bb; C = Cb; }
    else                      { B = Bc; bias = bc; C = Cc; }

    int tid = threadIdx.x;
    int tx  = tid & 15;
    int ty  = tid >> 4;
    int m0  = blockIdx.x * BM;

    float acc[8][8];
#pragma unroll
    for (int r = 0; r < 8; r++)
#pragma unroll
        for (int c = 0; c < 8; c++) acc[r][c] = 0.f;

    for (int k0 = 0; k0 < 128; k0 += BK) {
#pragma unroll
        for (int i = 0; i < 4; i++) {
            int idx = tid + i * 256;     // 0..1023
            int row = idx & 127;
            int kq  = idx >> 7;          // 0..7
            float4 v = make_float4(0.f, 0.f, 0.f, 0.f);
            int m = m0 + row;
            if (m < M)
                v = *(const float4*)(A + (size_t)m * 128 + k0 + kq * 4);
            As[kq * 4 + 0][row] = v.x;
            As[kq * 4 + 1][row] = v.y;
            As[kq * 4 + 2][row] = v.z;
            As[kq * 4 + 3][row] = v.w;
            float4 w = *(const float4*)(B + (size_t)row * 128 + k0 + kq * 4);
            Bs[kq * 4 + 0][row] = w.x;
            Bs[kq * 4 + 1][row] = w.y;
            Bs[kq * 4 + 2][row] = w.z;
            Bs[kq * 4 + 3][row] = w.w;
        }
        __syncthreads();

#pragma unroll
        for (int kk = 0; kk < BK; kk++) {
            float4 a0 = *(const float4*)&As[kk][ty * 8];
            float4 a1 = *(const float4*)&As[kk][ty * 8 + 4];
            float4 b0 = *(const float4*)&Bs[kk][tx * 8];
            float4 b1 = *(const float4*)&Bs[kk][tx * 8 + 4];
            float a[8] = {a0.x, a0.y, a0.z, a0.w, a1.x, a1.y, a1.z, a1.w};
            float b[8] = {b0.x, b0.y, b0.z, b0.w, b1.x, b1.y, b1.z, b1.w};
#pragma unroll
            for (int r = 0; r < 8; r++)
#pragma unroll
                for (int c = 0; c < 8; c++)
                    acc[r][c] = fmaf(a[r], b[c], acc[r][c]);
        }
        __syncthreads();
    }

#pragma unroll
    for (int r = 0; r < 8; r++) {
        int m = m0 + ty * 8 + r;
        if (m >= M) continue;
#pragma unroll
        for (int c = 0; c < 8; c += 4) {
            int n = tx * 8 + c;
            float4 o;
            o.x = acc[r][c + 0] + bias[n + 0];
            o.y = acc[r][c + 1] + bias[n + 1];
            o.z = acc[r][c + 2] + bias[n + 2];
            o.w = acc[r][c + 3] + bias[n + 3];
            if (relu) {
                o.x = fmaxf(o.x, 0.f);
                o.y = fmaxf(o.y, 0.f);
                o.z = fmaxf(o.z, 0.f);
                o.w = fmaxf(o.w, 0.f);
            }
            *(float4*)(C + (size_t)m * 128 + n) = o;
        }
    }
}

// ---------------------------------------------------------------------------
// Warp per dst node: softmax-weighted aggregation of V[src] over CSR edges.
//   lane l holds float4 l of Q[dst] (head = l>>3) and accumulates acc/ssum.
//   per edge: gather K[src],V[src] coalesced; dot via 3 shfl; p = exp(s/sqrt32).
//   write normalized row: agg = acc / (ssum + 1e-8)   (max shift cancels)
// ---------------------------------------------------------------------------
__device__ __forceinline__ void edge_step(int sj, const float4& q,
                                          float4& acc, float& ssum, int lane)
{
    float4 k = ((const float4*)(g_K + (size_t)sj * 128))[lane];
    float4 v = ((const float4*)(g_V + (size_t)sj * 128))[lane];
    float part = q.x * k.x + q.y * k.y + q.z * k.z + q.w * k.w;
    part += __shfl_xor_sync(0xFFFFFFFFu, part, 1);
    part += __shfl_xor_sync(0xFFFFFFFFu, part, 2);
    part += __shfl_xor_sync(0xFFFFFFFFu, part, 4);
    float p = expf(part * 0.17677669529663687f);
    acc.x = fmaf(p, v.x, acc.x);
    acc.y = fmaf(p, v.y, acc.y);
    acc.z = fmaf(p, v.z, acc.z);
    acc.w = fmaf(p, v.w, acc.w);
    ssum += p;
}

__global__ __launch_bounds__(256)
void aggregate_kernel(int M)
{
    int w    = (int)(((long long)blockIdx.x * blockDim.x + threadIdx.x) >> 5);
    int lane = threadIdx.x & 31;
    if (w >= M) return;

    int start = g_off[w];
    int end   = g_cur[w];    // == g_off[w+1] after scatter

    float4 q = ((const float4*)(g_Q + (size_t)w * 128))[lane];
    float4 acc = make_float4(0.f, 0.f, 0.f, 0.f);
    float ssum = 0.f;

    int i = start;
    for (; i + 32 <= end; i += 32) {
        int s = g_srcs[i + lane];
#pragma unroll 4
        for (int j = 0; j < 32; j++) {
            int sj = __shfl_sync(0xFFFFFFFFu, s, j);
            edge_step(sj, q, acc, ssum, lane);
        }
    }
    if (i < end) {
        int rem = end - i;
        int s = (lane < rem) ? g_srcs[i + lane] : 0;
        for (int j = 0; j < rem; j++) {
            int sj = __shfl_sync(0xFFFFFFFFu, s, j);
            edge_step(sj, q, acc, ssum, lane);
        }
    }

    float inv = 1.f / (ssum + 1e-8f);
    float4 o = make_float4(acc.x * inv, acc.y * inv, acc.z * inv, acc.w * inv);
    ((float4*)(g_agg + (size_t)w * 128))[lane] = o;
}

// ---------------------------------------------------------------------------
extern "C" void kernel_launch(void* const* d_in, const int* in_sizes, int n_in,
                              void* d_out, int out_size)
{
    const float* x  = (const float*)d_in[0];
    const void*  ei = d_in[1];
    const float* Wq = (const float*)d_in[2];
    const float* bq = (const float*)d_in[3];
    const float* Wk = (const float*)d_in[4];
    const float* bk = (const float*)d_in[5];
    const float* Wv = (const float*)d_in[6];
    const float* bv = (const float*)d_in[7];
    const float* Wo = (const float*)d_in[8];
    const float* bo = (const float*)d_in[9];
    float*       out = (float*)d_out;

    int M = in_sizes[0] / 128;   // nodes
    int E = in_sizes[1] / 2;     // edges

    float *pQ, *pK, *pV, *pAgg;
    cudaGetSymbolAddress((void**)&pQ,   g_Q);
    cudaGetSymbolAddress((void**)&pK,   g_K);
    cudaGetSymbolAddress((void**)&pV,   g_V);
    cudaGetSymbolAddress((void**)&pAgg, g_agg);

    detect_kernel<<<1, 32>>>((const unsigned*)ei);
    zero_deg<<<(M + 255) / 256, 256>>>(M);
    hist_kernel<<<(E + 255) / 256, 256>>>(ei, E, M);
    scan_kernel<<<1, 1024>>>(M);
    scatter_kernel<<<(E + 255) / 256, 256>>>(ei, E, M);

    dim3 gqkv((M + BM - 1) / BM, 3);
    gemm_kernel<<<gqkv, 256>>>(x, M, Wq, Wk, Wv, bq, bk, bv, pQ, pK, pV, 0);

    long long wt = (long long)M * 32;
    aggregate_kernel<<<(int)((wt + 255) / 256), 256>>>(M);

    dim3 gout((M + BM - 1) / BM, 1);
    gemm_kernel<<<gout, 256>>>(pAgg, M, Wo, Wo, Wo, bo, bo, bo, out, out, out, 1);
}

// round 5
// speedup vs baseline: 2.3347x; 1.1769x over previous
#include <cuda_runtime.h>

// ---------------------------------------------------------------------------
// GAT layer, CSR-gather version:
//   1. detect idx dtype, zero degree counters
//   2. counting sort edges by dst: histogram -> multi-block scan -> scatter
//   3. QKV GEMM (fused 3-in-1)
//   4. aggregate: warp per dst; gather K/V[src], softmax accumulate in regs,
//      write normalized agg row (no atomics; global max cancels in ratio)
//   5. output GEMM + bias + relu
// ---------------------------------------------------------------------------

#define MAXN 50048
#define MAXE 1600000
#define SCAN_BLK 1024
#define MAX_SBLKS 64

__device__ float g_Q[MAXN * 128];
__device__ float g_K[MAXN * 128];
__device__ float g_V[MAXN * 128];
__device__ float g_agg[MAXN * 128];
__device__ int   g_off[MAXN + 1];   // CSR row starts
__device__ int   g_cur[MAXN];       // scatter cursors; == row end after sort
__device__ int   g_srcs[MAXE];      // src ids sorted by dst
__device__ int   g_bsum[MAX_SBLKS]; // per-block sums for scan
__device__ int   g_idx64;           // 1 if edge_index is int64, 0 if int32

__device__ __forceinline__ int load_idx(const void* ei, long long pos, int M) {
    int v;
    if (g_idx64) v = (int)((const long long*)ei)[pos];
    else         v = ((const int*)ei)[pos];
    v = v < 0 ? 0 : (v >= M ? M - 1 : v);   // defensive clamp
    return v;
}

// ---------------------------------------------------------------------------
__global__ void detect_kernel(const unsigned* __restrict__ ei_u32) {
    if (threadIdx.x == 0 && blockIdx.x == 0) {
        int is64 = 1;
        for (int i = 0; i < 128; i++)
            if (ei_u32[2 * i + 1] != 0u) { is64 = 0; break; }
        g_idx64 = is64;
    }
}

__global__ void zero_deg(int M) {
    int t = blockIdx.x * blockDim.x + threadIdx.x;
    if (t < M) g_off[t] = 0;          // reuse g_off as degree counter
}

// histogram of dst
__global__ void hist_kernel(const void* __restrict__ ei, int E, int M) {
    int t = blockIdx.x * blockDim.x + threadIdx.x;
    if (t >= E) return;
    int dst = load_idx(ei, (long long)E + t, M);
    atomicAdd(&g_off[dst], 1);
}

// ---------------------------------------------------------------------------
// Multi-block exclusive scan of g_off[0..M) (degrees -> offsets).
// Phase 1: per-block exclusive scan (warp shuffle + smem combine), block sums out.
// ---------------------------------------------------------------------------
__global__ void scan_partial(int M) {
    __shared__ int wsum[32];
    int tid  = threadIdx.x;
    int gi   = blockIdx.x * SCAN_BLK + tid;
    int lane = tid & 31;
    int wid  = tid >> 5;

    int v = (gi < M) ? g_off[gi] : 0;

    // warp inclusive scan
    int x = v;
#pragma unroll
    for (int o = 1; o < 32; o <<= 1) {
        int y = __shfl_up_sync(0xFFFFFFFFu, x, o);
        if (lane >= o) x += y;
    }
    if (lane == 31) wsum[wid] = x;
    __syncthreads();

    if (wid == 0) {
        int w = (lane < 32) ? wsum[lane] : 0;
#pragma unroll
        for (int o = 1; o < 32; o <<= 1) {
            int y = __shfl_up_sync(0xFFFFFFFFu, w, o);
            if (lane >= o) w += y;
        }
        wsum[lane] = w;
    }
    __syncthreads();

    int incl = x + (wid > 0 ? wsum[wid - 1] : 0);
    int excl = incl - v;
    if (gi < M) g_off[gi] = excl;        // block-local exclusive for now
    if (tid == SCAN_BLK - 1) g_bsum[blockIdx.x] = incl;
}

// Phase 2: exclusive scan of block sums (single warp-scale block).
__global__ void scan_bsums(int nb) {
    int lane = threadIdx.x;
    int v = (lane < nb) ? g_bsum[lane] : 0;
    int x = v;
#pragma unroll
    for (int o = 1; o < 64; o <<= 1) {
        int y = __shfl_up_sync(0xFFFFFFFFu, x, o & 31);
        // 64-wide scan via two warps + smem
        (void)y;
        break;
    }
    // simple smem scan (nb <= 64, trivial cost)
    __shared__ int s[MAX_SBLKS];
    if (lane < MAX_SBLKS) s[lane] = (lane < nb) ? v : 0;
    __syncthreads();
    if (lane == 0) {
        int run = 0;
        for (int i = 0; i < nb; i++) { int t = s[i]; s[i] = run; run += t; }
        s[MAX_SBLKS - 1 >= nb ? nb : MAX_SBLKS - 1] = run; // total at s[nb]
    }
    __syncthreads();
    if (lane < nb) g_bsum[lane] = s[lane];
    if (lane == 0 && nb < MAX_SBLKS) g_bsum[nb] = s[nb];
}

// Phase 3: add block offsets; init cursors; set g_off[M] = total.
__global__ void scan_add(int M) {
    int tid = threadIdx.x;
    int gi  = blockIdx.x * SCAN_BLK + tid;
    if (gi < M) {
        int o = g_off[gi] + g_bsum[blockIdx.x];
        g_off[gi] = o;
        g_cur[gi] = o;
    }
    if (gi == M) {
        int nb = (M + SCAN_BLK - 1) / SCAN_BLK;
        g_off[M] = g_bsum[nb];
    }
}

// scatter src ids into dst-sorted order
__global__ void scatter_kernel(const void* __restrict__ ei, int E, int M) {
    int t = blockIdx.x * blockDim.x + threadIdx.x;
    if (t >= E) return;
    int src = load_idx(ei, t, M);
    int dst = load_idx(ei, (long long)E + t, M);
    int pos = atomicAdd(&g_cur[dst], 1);
    g_srcs[pos] = src;
}

// ---------------------------------------------------------------------------
// Tiled fp32 GEMM: C[M,128] = A[M,128] @ B[128,128]^T + bias (+relu).
// blockIdx.y selects among up to 3 (B, bias, C) triples (fused QKV).
// ---------------------------------------------------------------------------
#define BM 128
#define BN 128
#define BK 32

__global__ __launch_bounds__(256, 2)
void gemm_kernel(const float* __restrict__ A, int M,
                 const float* __restrict__ Ba, const float* __restrict__ Bb,
                 const float* __restrict__ Bc,
                 const float* __restrict__ ba, const float* __restrict__ bb,
                 const float* __restrict__ bc,
                 float* __restrict__ Ca, float* __restrict__ Cb,
                 float* __restrict__ Cc,
                 int relu)
{
    __shared__ float As[BK][BM + 4];
    __shared__ float Bs[BK][BN + 4];

    const float* B;
    const float* bias;
    float*       C;
    if (blockIdx.y == 0)      { B = Ba; bias = ba; C = Ca; }
    else if (blockIdx.y == 1) { B = Bb; bias = bb; C = Cb; }
    else                      { B = Bc; bias = bc; C = Cc; }

    int tid = threadIdx.x;
    int tx  = tid & 15;
    int ty  = tid >> 4;
    int m0  = blockIdx.x * BM;

    float acc[8][8];
#pragma unroll
    for (int r = 0; r < 8; r++)
#pragma unroll
        for (int c = 0; c < 8; c++) acc[r][c] = 0.f;

    for (int k0 = 0; k0 < 128; k0 += BK) {
#pragma unroll
        for (int i = 0; i < 4; i++) {
            int idx = tid + i * 256;     // 0..1023
            int row = idx & 127;
            int kq  = idx >> 7;          // 0..7
            float4 v = make_float4(0.f, 0.f, 0.f, 0.f);
            int m = m0 + row;
            if (m < M)
                v = *(const float4*)(A + (size_t)m * 128 + k0 + kq * 4);
            As[kq * 4 + 0][row] = v.x;
            As[kq * 4 + 1][row] = v.y;
            As[kq * 4 + 2][row] = v.z;
            As[kq * 4 + 3][row] = v.w;
            float4 w = *(const float4*)(B + (size_t)row * 128 + k0 + kq * 4);
            Bs[kq * 4 + 0][row] = w.x;
            Bs[kq * 4 + 1][row] = w.y;
            Bs[kq * 4 + 2][row] = w.z;
            Bs[kq * 4 + 3][row] = w.w;
        }
        __syncthreads();

#pragma unroll
        for (int kk = 0; kk < BK; kk++) {
            float4 a0 = *(const float4*)&As[kk][ty * 8];
            float4 a1 = *(const float4*)&As[kk][ty * 8 + 4];
            float4 b0 = *(const float4*)&Bs[kk][tx * 8];
            float4 b1 = *(const float4*)&Bs[kk][tx * 8 + 4];
            float a[8] = {a0.x, a0.y, a0.z, a0.w, a1.x, a1.y, a1.z, a1.w};
            float b[8] = {b0.x, b0.y, b0.z, b0.w, b1.x, b1.y, b1.z, b1.w};
#pragma unroll
            for (int r = 0; r < 8; r++)
#pragma unroll
                for (int c = 0; c < 8; c++)
                    acc[r][c] = fmaf(a[r], b[c], acc[r][c]);
        }
        __syncthreads();
    }

#pragma unroll
    for (int r = 0; r < 8; r++) {
        int m = m0 + ty * 8 + r;
        if (m >= M) continue;
#pragma unroll
        for (int c = 0; c < 8; c += 4) {
            int n = tx * 8 + c;
            float4 o;
            o.x = acc[r][c + 0] + bias[n + 0];
            o.y = acc[r][c + 1] + bias[n + 1];
            o.z = acc[r][c + 2] + bias[n + 2];
            o.w = acc[r][c + 3] + bias[n + 3];
            if (relu) {
                o.x = fmaxf(o.x, 0.f);
                o.y = fmaxf(o.y, 0.f);
                o.z = fmaxf(o.z, 0.f);
                o.w = fmaxf(o.w, 0.f);
            }
            *(float4*)(C + (size_t)m * 128 + n) = o;
        }
    }
}

// ---------------------------------------------------------------------------
// Warp per dst node: softmax-weighted aggregation of V[src] over CSR edges.
// ---------------------------------------------------------------------------
__device__ __forceinline__ void edge_step(int sj, const float4& q,
                                          float4& acc, float& ssum, int lane)
{
    float4 k = ((const float4*)(g_K + (size_t)sj * 128))[lane];
    float4 v = ((const float4*)(g_V + (size_t)sj * 128))[lane];
    float part = q.x * k.x + q.y * k.y + q.z * k.z + q.w * k.w;
    part += __shfl_xor_sync(0xFFFFFFFFu, part, 1);
    part += __shfl_xor_sync(0xFFFFFFFFu, part, 2);
    part += __shfl_xor_sync(0xFFFFFFFFu, part, 4);
    float p = expf(part * 0.17677669529663687f);
    acc.x = fmaf(p, v.x, acc.x);
    acc.y = fmaf(p, v.y, acc.y);
    acc.z = fmaf(p, v.z, acc.z);
    acc.w = fmaf(p, v.w, acc.w);
    ssum += p;
}

__global__ __launch_bounds__(256)
void aggregate_kernel(int M)
{
    int w    = (int)(((long long)blockIdx.x * blockDim.x + threadIdx.x) >> 5);
    int lane = threadIdx.x & 31;
    if (w >= M) return;

    int start = g_off[w];
    int end   = g_cur[w];    // == g_off[w+1] after scatter

    float4 q = ((const float4*)(g_Q + (size_t)w * 128))[lane];
    float4 acc = make_float4(0.f, 0.f, 0.f, 0.f);
    float ssum = 0.f;

    int i = start;
    for (; i + 32 <= end; i += 32) {
        int s = g_srcs[i + lane];
#pragma unroll 4
        for (int j = 0; j < 32; j++) {
            int sj = __shfl_sync(0xFFFFFFFFu, s, j);
            edge_step(sj, q, acc, ssum, lane);
        }
    }
    if (i < end) {
        int rem = end - i;
        int s = (lane < rem) ? g_srcs[i + lane] : 0;
        for (int j = 0; j < rem; j++) {
            int sj = __shfl_sync(0xFFFFFFFFu, s, j);
            edge_step(sj, q, acc, ssum, lane);
        }
    }

    float inv = 1.f / (ssum + 1e-8f);
    float4 o = make_float4(acc.x * inv, acc.y * inv, acc.z * inv, acc.w * inv);
    ((float4*)(g_agg + (size_t)w * 128))[lane] = o;
}

// ---------------------------------------------------------------------------
extern "C" void kernel_launch(void* const* d_in, const int* in_sizes, int n_in,
                              void* d_out, int out_size)
{
    const float* x  = (const float*)d_in[0];
    const void*  ei = d_in[1];
    const float* Wq = (const float*)d_in[2];
    const float* bq = (const float*)d_in[3];
    const float* Wk = (const float*)d_in[4];
    const float* bk = (const float*)d_in[5];
    const float* Wv = (const float*)d_in[6];
    const float* bv = (const float*)d_in[7];
    const float* Wo = (const float*)d_in[8];
    const float* bo = (const float*)d_in[9];
    float*       out = (float*)d_out;

    int M = in_sizes[0] / 128;   // nodes
    int E = in_sizes[1] / 2;     // edges

    float *pQ, *pK, *pV, *pAgg;
    cudaGetSymbolAddress((void**)&pQ,   g_Q);
    cudaGetSymbolAddress((void**)&pK,   g_K);
    cudaGetSymbolAddress((void**)&pV,   g_V);
    cudaGetSymbolAddress((void**)&pAgg, g_agg);

    int nb = (M + SCAN_BLK - 1) / SCAN_BLK;   // 49 for M=50000

    detect_kernel<<<1, 32>>>((const unsigned*)ei);
    zero_deg<<<(M + 255) / 256, 256>>>(M);
    hist_kernel<<<(E + 255) / 256, 256>>>(ei, E, M);
    scan_partial<<<nb, SCAN_BLK>>>(M);
    scan_bsums<<<1, MAX_SBLKS>>>(nb);
    scan_add<<<nb + 1, SCAN_BLK>>>(M);
    scatter_kernel<<<(E + 255) / 256, 256>>>(ei, E, M);

    dim3 gqkv((M + BM - 1) / BM, 3);
    gemm_kernel<<<gqkv, 256>>>(x, M, Wq, Wk, Wv, bq, bk, bv, pQ, pK, pV, 0);

    long long wt = (long long)M * 32;
    aggregate_kernel<<<(int)((wt + 255) / 256), 256>>>(M);

    dim3 gout((M + BM - 1) / BM, 1);
    gemm_kernel<<<gout, 256>>>(pAgg, M, Wo, Wo, Wo, bo, bo, bo, out, out, out, 1);
}